// round 5
// baseline (speedup 1.0000x reference)
#include <cuda_runtime.h>
#include <math.h>

#define NN 100000
#define EE 1600000
#define FIN 128
#define HD  64
#define CC  40
#define LL  6

// ---------------- scratch (static device allocation; no cudaMalloc) ----------------
__device__ int   g_deg[NN];
__device__ int   g_rowptr[NN + 1];
__device__ int   g_fill[NN];
__device__ float g_dis[NN];
__device__ int   g_colidx[EE];
__device__ float g_bufA[(size_t)NN * HD];   // ping: dis-scaled pre-aggregation features
__device__ float g_bufB[(size_t)NN * HD];   // pong
__device__ float g_jk[(size_t)NN * HD];     // running JumpingKnowledge max

// ---------------- graph preprocessing ----------------
__global__ void k_count(const int* __restrict__ dst) {
    int e = blockIdx.x * blockDim.x + threadIdx.x;
    if (e < EE) atomicAdd(&g_deg[dst[e]], 1);
}

// Single-block exclusive scan + init (fill, dis) fused.
__global__ void k_scan() {
    __shared__ int sh[1024];
    int tid = threadIdx.x;
    const int SEG = (NN + 1023) / 1024;   // 98
    int beg = tid * SEG;
    int end = min(beg + SEG, NN);
    int s = 0;
    for (int i = beg; i < end; i++) s += g_deg[i];
    sh[tid] = s;
    __syncthreads();
    for (int off = 1; off < 1024; off <<= 1) {
        int t = (tid >= off) ? sh[tid - off] : 0;
        __syncthreads();
        sh[tid] += t;
        __syncthreads();
    }
    int run = sh[tid] - s;                 // exclusive prefix for this segment
    for (int i = beg; i < end; i++) {
        int d = g_deg[i];
        g_rowptr[i] = run;
        g_fill[i]   = run;
        g_dis[i]    = rsqrtf((float)(d + 1));   // +1: self loop
        run += d;
    }
    if (tid == 1023) g_rowptr[NN] = sh[1023];   // == EE
}

__global__ void k_scatter(const int* __restrict__ src, const int* __restrict__ dst) {
    int e = blockIdx.x * blockDim.x + threadIdx.x;
    if (e < EE) {
        int p = atomicAdd(&g_fill[dst[e]], 1);
        g_colidx[p] = src[e];
    }
}

// ---------------- layer-0 GEMM:  hn[row,:] = dis[row] * (x[row,:] @ W0)  ----------------
__global__ void k_gemm0(const float* __restrict__ A, const float* __restrict__ W,
                        float* __restrict__ out) {
    __shared__ float As[64][68];
    __shared__ float Bs[64][68];
    int tid = threadIdx.x;
    int tx = tid & 15, ty = tid >> 4;
    int brow = blockIdx.x * 64;
    float acc[4][4] = {};

    for (int kc = 0; kc < FIN; kc += 64) {
        int c4 = tx * 4;
        #pragma unroll
        for (int i = 0; i < 4; i++) {
            int r = ty + 16 * i;
            int row = brow + r;
            float4 v = make_float4(0.f, 0.f, 0.f, 0.f);
            if (row < NN) v = *(const float4*)&A[(size_t)row * FIN + kc + c4];
            *(float4*)&As[r][c4] = v;
        }
        #pragma unroll
        for (int i = 0; i < 4; i++) {
            int kr = ty + 16 * i;
            *(float4*)&Bs[kr][c4] = *(const float4*)&W[(size_t)(kc + kr) * HD + c4];
        }
        __syncthreads();

        #pragma unroll
        for (int k = 0; k < 64; k++) {
            float a0 = As[ty * 4 + 0][k];
            float a1 = As[ty * 4 + 1][k];
            float a2 = As[ty * 4 + 2][k];
            float a3 = As[ty * 4 + 3][k];
            float4 b = *(float4*)&Bs[k][tx * 4];
            acc[0][0] += a0 * b.x; acc[0][1] += a0 * b.y; acc[0][2] += a0 * b.z; acc[0][3] += a0 * b.w;
            acc[1][0] += a1 * b.x; acc[1][1] += a1 * b.y; acc[1][2] += a1 * b.z; acc[1][3] += a1 * b.w;
            acc[2][0] += a2 * b.x; acc[2][1] += a2 * b.y; acc[2][2] += a2 * b.z; acc[2][3] += a2 * b.w;
            acc[3][0] += a3 * b.x; acc[3][1] += a3 * b.y; acc[3][2] += a3 * b.z; acc[3][3] += a3 * b.w;
        }
        __syncthreads();
    }

    #pragma unroll
    for (int i = 0; i < 4; i++) {
        int row = brow + ty * 4 + i;
        if (row < NN) {
            float d = g_dis[row];
            float4 o = make_float4(acc[i][0] * d, acc[i][1] * d, acc[i][2] * d, acc[i][3] * d);
            *(float4*)&out[(size_t)row * HD + tx * 4] = o;
        }
    }
}

// ---------------- R1-style gather: warp per node, scalar uniform colidx, 4-wide ----------------
__device__ __forceinline__ float2 warp_gather_sum(const float* __restrict__ hn_in,
                                                  int v, int lane) {
    int beg = g_rowptr[v], end = g_rowptr[v + 1];
    size_t fo = (size_t)v * HD + lane * 2;
    float2 acc = *(const float2*)&hn_in[fo];   // self-loop term

    int p = beg;
    for (; p + 4 <= end; p += 4) {
        int u0 = g_colidx[p + 0];
        int u1 = g_colidx[p + 1];
        int u2 = g_colidx[p + 2];
        int u3 = g_colidx[p + 3];
        float2 t0 = *(const float2*)&hn_in[(size_t)u0 * HD + lane * 2];
        float2 t1 = *(const float2*)&hn_in[(size_t)u1 * HD + lane * 2];
        float2 t2 = *(const float2*)&hn_in[(size_t)u2 * HD + lane * 2];
        float2 t3 = *(const float2*)&hn_in[(size_t)u3 * HD + lane * 2];
        acc.x += (t0.x + t1.x) + (t2.x + t3.x);
        acc.y += (t0.y + t1.y) + (t2.y + t3.y);
    }
    for (; p < end; p++) {
        int u = g_colidx[p];
        float2 t = *(const float2*)&hn_in[(size_t)u * HD + lane * 2];
        acc.x += t.x; acc.y += t.y;
    }
    return acc;
}

// ---------------- fused: aggregate 64 nodes per block, then 64x64x64 GEMM ----------------
// h[v,:]  = relu(dis[v]*(hn_in[v,:] + sum hn_in[u,:]) + b)   (8 nodes per warp)
// jk      = first ? h : max(jk, h)
// hn_out[v,:] = dis[v] * (h[v,:] @ W)
__global__ void k_agg_gemm(const float* __restrict__ hn_in, float* __restrict__ hn_out,
                           const float* __restrict__ W, const float* __restrict__ bias,
                           int first) {
    __shared__ float Hs[64][68];   // 68: float4 rows stay 16B-aligned (272 B stride)
    __shared__ float Bs[64][68];
    int tid = threadIdx.x;
    int warp = tid >> 5, lane = tid & 31;
    int base = blockIdx.x * 64;

    // stage W (64x64) — consumed after the __syncthreads below
    {
        int tx = tid & 15, ty = tid >> 4;
        int c4 = tx * 4;
        #pragma unroll
        for (int i = 0; i < 4; i++) {
            int kr = ty + 16 * i;
            *(float4*)&Bs[kr][c4] = *(const float4*)&W[(size_t)kr * HD + c4];
        }
    }

    // aggregation: warp handles 8 consecutive nodes
    float2 b2 = *(const float2*)&bias[lane * 2];
    #pragma unroll 1
    for (int j = 0; j < 8; j++) {
        int r = warp * 8 + j;
        int v = base + r;
        if (v < NN) {
            float2 acc = warp_gather_sum(hn_in, v, lane);
            float d = g_dis[v];
            float hx = fmaxf(fmaf(d, acc.x, b2.x), 0.f);
            float hy = fmaxf(fmaf(d, acc.y, b2.y), 0.f);
            Hs[r][lane * 2 + 0] = hx;
            Hs[r][lane * 2 + 1] = hy;
            size_t fo = (size_t)v * HD + lane * 2;
            if (first) {
                *(float2*)&g_jk[fo] = make_float2(hx, hy);
            } else {
                float2 jv = *(const float2*)&g_jk[fo];
                *(float2*)&g_jk[fo] = make_float2(fmaxf(jv.x, hx), fmaxf(jv.y, hy));
            }
        } else {
            Hs[r][lane * 2 + 0] = 0.f;
            Hs[r][lane * 2 + 1] = 0.f;
        }
    }
    __syncthreads();

    // GEMM: hn_out[base..base+63, :] = dis * (Hs @ Bs)
    int tx = tid & 15, ty = tid >> 4;
    float acc[4][4] = {};
    #pragma unroll
    for (int k = 0; k < 64; k++) {
        float a0 = Hs[ty * 4 + 0][k];
        float a1 = Hs[ty * 4 + 1][k];
        float a2 = Hs[ty * 4 + 2][k];
        float a3 = Hs[ty * 4 + 3][k];
        float4 b = *(float4*)&Bs[k][tx * 4];
        acc[0][0] += a0 * b.x; acc[0][1] += a0 * b.y; acc[0][2] += a0 * b.z; acc[0][3] += a0 * b.w;
        acc[1][0] += a1 * b.x; acc[1][1] += a1 * b.y; acc[1][2] += a1 * b.z; acc[1][3] += a1 * b.w;
        acc[2][0] += a2 * b.x; acc[2][1] += a2 * b.y; acc[2][2] += a2 * b.z; acc[2][3] += a2 * b.w;
        acc[3][0] += a3 * b.x; acc[3][1] += a3 * b.y; acc[3][2] += a3 * b.z; acc[3][3] += a3 * b.w;
    }
    #pragma unroll
    for (int i = 0; i < 4; i++) {
        int row = base + ty * 4 + i;
        if (row < NN) {
            float d = g_dis[row];
            float4 o = make_float4(acc[i][0] * d, acc[i][1] * d, acc[i][2] * d, acc[i][3] * d);
            *(float4*)&hn_out[(size_t)row * HD + tx * 4] = o;
        }
    }
}

// Last layer: warp per node, only jk update, no h store, no GEMM.
__global__ void k_agg_last(const float* __restrict__ hn_in, const float* __restrict__ bias) {
    int warp = (blockIdx.x * blockDim.x + threadIdx.x) >> 5;
    int lane = threadIdx.x & 31;
    if (warp >= NN) return;
    int v = warp;

    float2 acc = warp_gather_sum(hn_in, v, lane);
    float d = g_dis[v];
    float2 b = *(const float2*)&bias[lane * 2];
    float hx = fmaxf(fmaf(d, acc.x, b.x), 0.f);
    float hy = fmaxf(fmaf(d, acc.y, b.y), 0.f);

    size_t fo = (size_t)v * HD + lane * 2;
    float2 j = *(const float2*)&g_jk[fo];
    *(float2*)&g_jk[fo] = make_float2(fmaxf(j.x, hx), fmaxf(j.y, hy));
}

// ---------------- head: warp per row, jk @ fc_w + fc_b, log_softmax ----------------
__global__ void k_proj(const float* __restrict__ fcw, const float* __restrict__ fcb,
                       float* __restrict__ out) {
    __shared__ float Wsm[HD * CC];
    __shared__ float bsm[CC];
    int tid = threadIdx.x;
    for (int i = tid; i < HD * CC; i += blockDim.x) Wsm[i] = fcw[i];
    if (tid < CC) bsm[tid] = fcb[tid];
    __syncthreads();

    int warp = (blockIdx.x * blockDim.x + tid) >> 5;
    int lane = tid & 31;
    if (warp >= NN) return;
    int v = warp;

    float2 jv = *(const float2*)&g_jk[(size_t)v * HD + lane * 2];
    bool act = lane < 20;                   // 20 lanes x 2 cols = 40
    int c0 = lane * 2;
    float a0 = 0.f, a1 = 0.f;
    #pragma unroll
    for (int k = 0; k < HD; k++) {
        float hv = __shfl_sync(0xffffffffu, (k & 1) ? jv.y : jv.x, k >> 1);
        if (act) {
            float2 w = *(const float2*)&Wsm[k * CC + c0];
            a0 = fmaf(hv, w.x, a0);
            a1 = fmaf(hv, w.y, a1);
        }
    }
    if (act) { a0 += bsm[c0]; a1 += bsm[c0 + 1]; }

    float m = act ? fmaxf(a0, a1) : -INFINITY;
    #pragma unroll
    for (int off = 16; off; off >>= 1) m = fmaxf(m, __shfl_xor_sync(0xffffffffu, m, off));
    float s = act ? (expf(a0 - m) + expf(a1 - m)) : 0.f;
    #pragma unroll
    for (int off = 16; off; off >>= 1) s += __shfl_xor_sync(0xffffffffu, s, off);
    float lse = m + logf(s);

    if (act) {
        float2 o = make_float2(a0 - lse, a1 - lse);
        *(float2*)&out[(size_t)v * CC + c0] = o;
    }
}

// ---------------- launch ----------------
extern "C" void kernel_launch(void* const* d_in, const int* in_sizes, int n_in,
                              void* d_out, int out_size) {
    const float* x   = (const float*)d_in[0];
    const int*   ei  = (const int*)  d_in[1];
    const float* W0  = (const float*)d_in[2];
    const float* Ws  = (const float*)d_in[3];
    const float* bs  = (const float*)d_in[4];
    const float* fcw = (const float*)d_in[5];
    const float* fcb = (const float*)d_in[6];
    float* out = (float*)d_out;

    const int* src = ei;         // edge_index[0]
    const int* dst = ei + EE;    // edge_index[1]

    int* degp; float* bufA; float* bufB;
    cudaGetSymbolAddress((void**)&degp, g_deg);
    cudaGetSymbolAddress((void**)&bufA, g_bufA);
    cudaGetSymbolAddress((void**)&bufB, g_bufB);

    // CSR build (once per call, reused by all 6 layers)
    cudaMemsetAsync(degp, 0, NN * sizeof(int));
    k_count   <<<(EE + 255) / 256, 256>>>(dst);
    k_scan    <<<1, 1024>>>();
    k_scatter <<<(EE + 255) / 256, 256>>>(src, dst);

    const int TILE_GRID = (NN + 63) / 64;   // 1563
    const int AGG_GRID  = (NN + 7) / 8;     // warp-per-node kernels

    // layer 0: x (N x 128) @ W0 -> bufA (dis-scaled)
    k_gemm0<<<TILE_GRID, 256>>>(x, W0, bufA);

    // layers 0..4: fused aggregation + next-layer GEMM
    float* cur = bufA; float* nxt = bufB;
    for (int l = 0; l < LL - 1; l++) {
        k_agg_gemm<<<TILE_GRID, 256>>>(cur, nxt, Ws + (size_t)l * HD * HD,
                                       bs + (size_t)l * HD, l == 0);
        float* t = cur; cur = nxt; nxt = t;
    }
    // layer 5: aggregation only (jk update)
    k_agg_last<<<AGG_GRID, 256>>>(cur, bs + (size_t)(LL - 1) * HD);

    // head
    k_proj<<<AGG_GRID, 256>>>(fcw, fcb, out);
}

// round 6
// speedup vs baseline: 1.1689x; 1.1689x over previous
#include <cuda_runtime.h>
#include <cuda_fp16.h>
#include <math.h>

#define NN 100000
#define EE 1600000
#define FIN 128
#define HD  64
#define CC  40
#define LL  6

// ---------------- scratch (static device allocation; no cudaMalloc) ----------------
__device__ int    g_deg[NN];
__device__ int    g_rowptr[NN + 1];
__device__ int    g_fill[NN];
__device__ float  g_dis[NN];
__device__ int    g_colidx[EE];
__device__ __half g_hn[(size_t)NN * HD];  // fp16 dis-scaled pre-aggregation features
__device__ float  g_h [(size_t)NN * HD];  // post-relu layer output (fp32, GEMM input)
__device__ float  g_jk[(size_t)NN * HD];  // running JumpingKnowledge max (fp32)

// ---------------- graph preprocessing ----------------
__global__ void k_count(const int* __restrict__ dst) {
    int e = blockIdx.x * blockDim.x + threadIdx.x;
    if (e < EE) atomicAdd(&g_deg[dst[e]], 1);
}

// Single-block exclusive scan + init (fill, dis) fused.
__global__ void k_scan() {
    __shared__ int sh[1024];
    int tid = threadIdx.x;
    const int SEG = (NN + 1023) / 1024;   // 98
    int beg = tid * SEG;
    int end = min(beg + SEG, NN);
    int s = 0;
    for (int i = beg; i < end; i++) s += g_deg[i];
    sh[tid] = s;
    __syncthreads();
    for (int off = 1; off < 1024; off <<= 1) {
        int t = (tid >= off) ? sh[tid - off] : 0;
        __syncthreads();
        sh[tid] += t;
        __syncthreads();
    }
    int run = sh[tid] - s;                 // exclusive prefix for this segment
    for (int i = beg; i < end; i++) {
        int d = g_deg[i];
        g_rowptr[i] = run;
        g_fill[i]   = run;
        g_dis[i]    = rsqrtf((float)(d + 1));   // +1: self loop
        run += d;
    }
    if (tid == 1023) g_rowptr[NN] = sh[1023];   // == EE
}

__global__ void k_scatter(const int* __restrict__ src, const int* __restrict__ dst) {
    int e = blockIdx.x * blockDim.x + threadIdx.x;
    if (e < EE) {
        int p = atomicAdd(&g_fill[dst[e]], 1);
        g_colidx[p] = src[e];
    }
}

// ---------------- GEMM:  hn[row,:] = fp16( dis[row] * (A[row,:] @ W) )  ----------------
// 64x64 output tile, K staged in 64-wide chunks, 4x4 microtile per thread (256 thr).
template<int K, bool FROMX>
__global__ void k_gemm(const float* __restrict__ Aext, const float* __restrict__ W) {
    __shared__ float As[64][68];
    __shared__ float Bs[64][68];
    const float* __restrict__ A = FROMX ? Aext : (const float*)g_h;
    int tid = threadIdx.x;
    int tx = tid & 15, ty = tid >> 4;
    int brow = blockIdx.x * 64;
    float acc[4][4] = {};

    for (int kc = 0; kc < K; kc += 64) {
        int c4 = tx * 4;
        #pragma unroll
        for (int i = 0; i < 4; i++) {
            int r = ty + 16 * i;
            int row = brow + r;
            float4 v = make_float4(0.f, 0.f, 0.f, 0.f);
            if (row < NN) v = *(const float4*)&A[(size_t)row * K + kc + c4];
            *(float4*)&As[r][c4] = v;
        }
        #pragma unroll
        for (int i = 0; i < 4; i++) {
            int kr = ty + 16 * i;
            *(float4*)&Bs[kr][c4] = *(const float4*)&W[(size_t)(kc + kr) * HD + c4];
        }
        __syncthreads();

        #pragma unroll
        for (int k = 0; k < 64; k++) {
            float a0 = As[ty * 4 + 0][k];
            float a1 = As[ty * 4 + 1][k];
            float a2 = As[ty * 4 + 2][k];
            float a3 = As[ty * 4 + 3][k];
            float4 b = *(float4*)&Bs[k][tx * 4];
            acc[0][0] += a0 * b.x; acc[0][1] += a0 * b.y; acc[0][2] += a0 * b.z; acc[0][3] += a0 * b.w;
            acc[1][0] += a1 * b.x; acc[1][1] += a1 * b.y; acc[1][2] += a1 * b.z; acc[1][3] += a1 * b.w;
            acc[2][0] += a2 * b.x; acc[2][1] += a2 * b.y; acc[2][2] += a2 * b.z; acc[2][3] += a2 * b.w;
            acc[3][0] += a3 * b.x; acc[3][1] += a3 * b.y; acc[3][2] += a3 * b.z; acc[3][3] += a3 * b.w;
        }
        __syncthreads();
    }

    #pragma unroll
    for (int i = 0; i < 4; i++) {
        int row = brow + ty * 4 + i;
        if (row < NN) {
            float d = g_dis[row];
            __half2 p0 = __floats2half2_rn(acc[i][0] * d, acc[i][1] * d);
            __half2 p1 = __floats2half2_rn(acc[i][2] * d, acc[i][3] * d);
            uint2 pk;
            pk.x = *(unsigned int*)&p0;
            pk.y = *(unsigned int*)&p1;
            *(uint2*)&g_hn[(size_t)row * HD + tx * 4] = pk;   // 8B aligned (tx*4 halves)
        }
    }
}

// ---------------- aggregation: warp per node, CSR pull (fp16 gather, fp32 accum) ----------------
__device__ __forceinline__ float2 warp_gather_sum(int v, int lane) {
    int beg = g_rowptr[v], end = g_rowptr[v + 1];
    const __half2* hn2 = (const __half2*)g_hn;
    int fo2 = v * (HD / 2) + lane;            // index in half2 units
    float2 acc = __half22float2(hn2[fo2]);    // self-loop term

    int p = beg;
    for (; p + 4 <= end; p += 4) {
        int u0 = g_colidx[p + 0];
        int u1 = g_colidx[p + 1];
        int u2 = g_colidx[p + 2];
        int u3 = g_colidx[p + 3];
        float2 t0 = __half22float2(hn2[u0 * (HD / 2) + lane]);
        float2 t1 = __half22float2(hn2[u1 * (HD / 2) + lane]);
        float2 t2 = __half22float2(hn2[u2 * (HD / 2) + lane]);
        float2 t3 = __half22float2(hn2[u3 * (HD / 2) + lane]);
        acc.x += (t0.x + t1.x) + (t2.x + t3.x);
        acc.y += (t0.y + t1.y) + (t2.y + t3.y);
    }
    for (; p < end; p++) {
        int u = g_colidx[p];
        float2 t = __half22float2(hn2[u * (HD / 2) + lane]);
        acc.x += t.x; acc.y += t.y;
    }
    return acc;
}

__global__ void k_agg(const float* __restrict__ bias, int first) {
    int warp = (blockIdx.x * blockDim.x + threadIdx.x) >> 5;
    int lane = threadIdx.x & 31;
    if (warp >= NN) return;
    int v = warp;

    float2 acc = warp_gather_sum(v, lane);
    float d = g_dis[v];
    float2 b = *(const float2*)&bias[lane * 2];
    float hx = fmaxf(fmaf(d, acc.x, b.x), 0.f);
    float hy = fmaxf(fmaf(d, acc.y, b.y), 0.f);

    size_t fo = (size_t)v * HD + lane * 2;
    *(float2*)&g_h[fo] = make_float2(hx, hy);
    if (first) {
        *(float2*)&g_jk[fo] = make_float2(hx, hy);
    } else {
        float2 j = *(const float2*)&g_jk[fo];
        *(float2*)&g_jk[fo] = make_float2(fmaxf(j.x, hx), fmaxf(j.y, hy));
    }
}

// Last layer: only jk update, no h store.
__global__ void k_agg_last(const float* __restrict__ bias) {
    int warp = (blockIdx.x * blockDim.x + threadIdx.x) >> 5;
    int lane = threadIdx.x & 31;
    if (warp >= NN) return;
    int v = warp;

    float2 acc = warp_gather_sum(v, lane);
    float d = g_dis[v];
    float2 b = *(const float2*)&bias[lane * 2];
    float hx = fmaxf(fmaf(d, acc.x, b.x), 0.f);
    float hy = fmaxf(fmaf(d, acc.y, b.y), 0.f);

    size_t fo = (size_t)v * HD + lane * 2;
    float2 j = *(const float2*)&g_jk[fo];
    *(float2*)&g_jk[fo] = make_float2(fmaxf(j.x, hx), fmaxf(j.y, hy));
}

// ---------------- head: warp per row, jk @ fc_w + fc_b, log_softmax ----------------
__global__ void k_proj(const float* __restrict__ fcw, const float* __restrict__ fcb,
                       float* __restrict__ out) {
    __shared__ float Wsm[HD * CC];
    __shared__ float bsm[CC];
    int tid = threadIdx.x;
    for (int i = tid; i < HD * CC; i += blockDim.x) Wsm[i] = fcw[i];
    if (tid < CC) bsm[tid] = fcb[tid];
    __syncthreads();

    int warp = (blockIdx.x * blockDim.x + tid) >> 5;
    int lane = tid & 31;
    if (warp >= NN) return;
    int v = warp;

    float2 jv = *(const float2*)&g_jk[(size_t)v * HD + lane * 2];
    bool act = lane < 20;                   // 20 lanes x 2 cols = 40
    int c0 = lane * 2;
    float a0 = 0.f, a1 = 0.f;
    #pragma unroll
    for (int k = 0; k < HD; k++) {
        float hv = __shfl_sync(0xffffffffu, (k & 1) ? jv.y : jv.x, k >> 1);
        if (act) {
            float2 w = *(const float2*)&Wsm[k * CC + c0];
            a0 = fmaf(hv, w.x, a0);
            a1 = fmaf(hv, w.y, a1);
        }
    }
    if (act) { a0 += bsm[c0]; a1 += bsm[c0 + 1]; }

    float m = act ? fmaxf(a0, a1) : -INFINITY;
    #pragma unroll
    for (int off = 16; off; off >>= 1) m = fmaxf(m, __shfl_xor_sync(0xffffffffu, m, off));
    float s = act ? (expf(a0 - m) + expf(a1 - m)) : 0.f;
    #pragma unroll
    for (int off = 16; off; off >>= 1) s += __shfl_xor_sync(0xffffffffu, s, off);
    float lse = m + logf(s);

    if (act) {
        float2 o = make_float2(a0 - lse, a1 - lse);
        *(float2*)&out[(size_t)v * CC + c0] = o;
    }
}

// ---------------- launch ----------------
extern "C" void kernel_launch(void* const* d_in, const int* in_sizes, int n_in,
                              void* d_out, int out_size) {
    const float* x   = (const float*)d_in[0];
    const int*   ei  = (const int*)  d_in[1];
    const float* W0  = (const float*)d_in[2];
    const float* Ws  = (const float*)d_in[3];
    const float* bs  = (const float*)d_in[4];
    const float* fcw = (const float*)d_in[5];
    const float* fcb = (const float*)d_in[6];
    float* out = (float*)d_out;

    const int* src = ei;         // edge_index[0]
    const int* dst = ei + EE;    // edge_index[1]

    int* degp;
    cudaGetSymbolAddress((void**)&degp, g_deg);

    // CSR build (once per call, reused by all 6 layers)
    cudaMemsetAsync(degp, 0, NN * sizeof(int));
    k_count   <<<(EE + 255) / 256, 256>>>(dst);
    k_scan    <<<1, 1024>>>();
    k_scatter <<<(EE + 255) / 256, 256>>>(src, dst);

    const int GEMM_GRID = (NN + 63) / 64;
    const int AGG_GRID  = (NN + 7) / 8;     // 8 warps per 256-thread block

    // layer 0: x (N x 128) @ W0
    k_gemm<FIN, true><<<GEMM_GRID, 256>>>(x, W0);
    k_agg<<<AGG_GRID, 256>>>(bs + 0 * HD, 1);

    // layers 1..4
    for (int l = 1; l < LL - 1; l++) {
        k_gemm<HD, false><<<GEMM_GRID, 256>>>(nullptr, Ws + (size_t)(l - 1) * HD * HD);
        k_agg<<<AGG_GRID, 256>>>(bs + (size_t)l * HD, 0);
    }
    // layer 5: no h store
    k_gemm<HD, false><<<GEMM_GRID, 256>>>(nullptr, Ws + (size_t)(LL - 2) * HD * HD);
    k_agg_last<<<AGG_GRID, 256>>>(bs + (size_t)(LL - 1) * HD);

    // head
    k_proj<<<AGG_GRID, 256>>>(fcw, fcb, out);
}

// round 7
// speedup vs baseline: 1.5947x; 1.3642x over previous
#include <cuda_runtime.h>
#include <math.h>

#define NN 100000
#define EE 1600000
#define FIN 128
#define HD  64
#define CC  40
#define LL  6
#define NB  ((NN + 255) / 256)   // 391 scan blocks

// ---------------- scratch (static device allocation; no cudaMalloc) ----------------
__device__ int   g_deg[NN];
__device__ int   g_rowptr[NN + 1];
__device__ int   g_fill[NN];
__device__ float g_dis[NN];
__device__ int   g_colidx[EE];
__device__ int   g_bsum[NB];
__device__ int   g_boff[NB];
__device__ float g_hn[(size_t)NN * HD];   // dis-scaled pre-aggregation features (fp32)
__device__ float g_h [(size_t)NN * HD];   // post-relu layer output
__device__ float g_jk[(size_t)NN * HD];   // running JumpingKnowledge max

// ---------------- graph preprocessing ----------------
__global__ void k_count(const int* __restrict__ dst) {
    int e = blockIdx.x * blockDim.x + threadIdx.x;
    if (e < EE) atomicAdd(&g_deg[dst[e]], 1);
}

// scan stage 1: per-block sums of deg (256 elems per block)
__global__ void k_scan1() {
    __shared__ int wsum[8];
    int tid = threadIdx.x, lane = tid & 31, w = tid >> 5;
    int i = blockIdx.x * 256 + tid;
    int d = (i < NN) ? g_deg[i] : 0;
    int s = d;
    #pragma unroll
    for (int off = 16; off; off >>= 1) s += __shfl_xor_sync(0xffffffffu, s, off);
    if (lane == 0) wsum[w] = s;
    __syncthreads();
    if (tid == 0) {
        int t = 0;
        #pragma unroll
        for (int k = 0; k < 8; k++) t += wsum[k];
        g_bsum[blockIdx.x] = t;
    }
}

// scan stage 2: single block, exclusive scan of 391 block sums
__global__ void k_scan2() {
    __shared__ int sh[512];
    int tid = threadIdx.x;
    int v = (tid < NB) ? g_bsum[tid] : 0;
    sh[tid] = v;
    __syncthreads();
    #pragma unroll
    for (int off = 1; off < 512; off <<= 1) {
        int t = (tid >= off) ? sh[tid - off] : 0;
        __syncthreads();
        sh[tid] += t;
        __syncthreads();
    }
    if (tid < NB) g_boff[tid] = sh[tid] - v;   // exclusive
    if (tid == 511) g_rowptr[NN] = sh[511];    // total == EE
}

// scan stage 3: block-local exclusive scan + global offset; init fill/dis
__global__ void k_scan3() {
    __shared__ int wsum[8];
    __shared__ int woff[8];
    int tid = threadIdx.x, lane = tid & 31, w = tid >> 5;
    int i = blockIdx.x * 256 + tid;
    int d = (i < NN) ? g_deg[i] : 0;
    // warp inclusive scan
    int x = d;
    #pragma unroll
    for (int off = 1; off < 32; off <<= 1) {
        int t = __shfl_up_sync(0xffffffffu, x, off);
        if (lane >= off) x += t;
    }
    if (lane == 31) wsum[w] = x;
    __syncthreads();
    if (w == 0 && lane < 8) {
        int v = wsum[lane];
        int y = v;
        #pragma unroll
        for (int off = 1; off < 8; off <<= 1) {
            int t = __shfl_up_sync(0xffu, y, off);
            if (lane >= off) y += t;
        }
        woff[lane] = y - v;   // exclusive over warps
    }
    __syncthreads();
    if (i < NN) {
        int excl = g_boff[blockIdx.x] + woff[w] + (x - d);
        g_rowptr[i] = excl;
        g_fill[i]   = excl;
        g_dis[i]    = rsqrtf((float)(d + 1));   // +1: self loop
    }
}

__global__ void k_scatter(const int* __restrict__ src, const int* __restrict__ dst) {
    int e = blockIdx.x * blockDim.x + threadIdx.x;
    if (e < EE) {
        int p = atomicAdd(&g_fill[dst[e]], 1);
        g_colidx[p] = src[e];
    }
}

// ---------------- GEMM:  hn[row,:] = dis[row] * (A[row,:] @ W)  ----------------
template<int K, bool FROMX>
__global__ void k_gemm(const float* __restrict__ Aext, const float* __restrict__ W) {
    __shared__ float As[64][68];
    __shared__ float Bs[64][68];
    const float* __restrict__ A = FROMX ? Aext : (const float*)g_h;
    int tid = threadIdx.x;
    int tx = tid & 15, ty = tid >> 4;
    int brow = blockIdx.x * 64;
    float acc[4][4] = {};

    for (int kc = 0; kc < K; kc += 64) {
        int c4 = tx * 4;
        #pragma unroll
        for (int i = 0; i < 4; i++) {
            int r = ty + 16 * i;
            int row = brow + r;
            float4 v = make_float4(0.f, 0.f, 0.f, 0.f);
            if (row < NN) v = *(const float4*)&A[(size_t)row * K + kc + c4];
            *(float4*)&As[r][c4] = v;
        }
        #pragma unroll
        for (int i = 0; i < 4; i++) {
            int kr = ty + 16 * i;
            *(float4*)&Bs[kr][c4] = *(const float4*)&W[(size_t)(kc + kr) * HD + c4];
        }
        __syncthreads();

        #pragma unroll
        for (int k = 0; k < 64; k++) {
            float a0 = As[ty * 4 + 0][k];
            float a1 = As[ty * 4 + 1][k];
            float a2 = As[ty * 4 + 2][k];
            float a3 = As[ty * 4 + 3][k];
            float4 b = *(float4*)&Bs[k][tx * 4];
            acc[0][0] += a0 * b.x; acc[0][1] += a0 * b.y; acc[0][2] += a0 * b.z; acc[0][3] += a0 * b.w;
            acc[1][0] += a1 * b.x; acc[1][1] += a1 * b.y; acc[1][2] += a1 * b.z; acc[1][3] += a1 * b.w;
            acc[2][0] += a2 * b.x; acc[2][1] += a2 * b.y; acc[2][2] += a2 * b.z; acc[2][3] += a2 * b.w;
            acc[3][0] += a3 * b.x; acc[3][1] += a3 * b.y; acc[3][2] += a3 * b.z; acc[3][3] += a3 * b.w;
        }
        __syncthreads();
    }

    #pragma unroll
    for (int i = 0; i < 4; i++) {
        int row = brow + ty * 4 + i;
        if (row < NN) {
            float d = g_dis[row];
            float4 o = make_float4(acc[i][0] * d, acc[i][1] * d, acc[i][2] * d, acc[i][3] * d);
            *(float4*)&g_hn[(size_t)row * HD + tx * 4] = o;
        }
    }
}

// ---------------- R1 gather: warp per node, scalar uniform colidx, 4-wide ----------------
__device__ __forceinline__ float2 warp_gather_sum(int v, int lane) {
    int beg = g_rowptr[v], end = g_rowptr[v + 1];
    size_t fo = (size_t)v * HD + lane * 2;
    float2 acc = *(const float2*)&g_hn[fo];   // self-loop term

    int p = beg;
    for (; p + 4 <= end; p += 4) {
        int u0 = g_colidx[p + 0];
        int u1 = g_colidx[p + 1];
        int u2 = g_colidx[p + 2];
        int u3 = g_colidx[p + 3];
        float2 t0 = *(const float2*)&g_hn[(size_t)u0 * HD + lane * 2];
        float2 t1 = *(const float2*)&g_hn[(size_t)u1 * HD + lane * 2];
        float2 t2 = *(const float2*)&g_hn[(size_t)u2 * HD + lane * 2];
        float2 t3 = *(const float2*)&g_hn[(size_t)u3 * HD + lane * 2];
        acc.x += (t0.x + t1.x) + (t2.x + t3.x);
        acc.y += (t0.y + t1.y) + (t2.y + t3.y);
    }
    for (; p < end; p++) {
        int u = g_colidx[p];
        float2 t = *(const float2*)&g_hn[(size_t)u * HD + lane * 2];
        acc.x += t.x; acc.y += t.y;
    }
    return acc;
}

__global__ void k_agg(const float* __restrict__ bias, int first) {
    int warp = (blockIdx.x * blockDim.x + threadIdx.x) >> 5;
    int lane = threadIdx.x & 31;
    if (warp >= NN) return;
    int v = warp;

    float2 acc = warp_gather_sum(v, lane);
    float d = g_dis[v];
    float2 b = *(const float2*)&bias[lane * 2];
    float hx = fmaxf(fmaf(d, acc.x, b.x), 0.f);
    float hy = fmaxf(fmaf(d, acc.y, b.y), 0.f);

    size_t fo = (size_t)v * HD + lane * 2;
    *(float2*)&g_h[fo] = make_float2(hx, hy);
    if (first) {
        *(float2*)&g_jk[fo] = make_float2(hx, hy);
    } else {
        float2 j = *(const float2*)&g_jk[fo];
        *(float2*)&g_jk[fo] = make_float2(fmaxf(j.x, hx), fmaxf(j.y, hy));
    }
}

// ---------------- last layer fused with head: agg -> jk-final (regs) -> proj -> log_softmax ----------------
__global__ void k_agg_proj(const float* __restrict__ bias,
                           const float* __restrict__ fcw, const float* __restrict__ fcb,
                           float* __restrict__ out) {
    __shared__ float Wsm[HD * CC];
    __shared__ float bsm[CC];
    int tid = threadIdx.x;
    for (int i = tid; i < HD * CC; i += blockDim.x) Wsm[i] = fcw[i];
    if (tid < CC) bsm[tid] = fcb[tid];
    __syncthreads();

    int warp = (blockIdx.x * blockDim.x + tid) >> 5;
    int lane = tid & 31;
    if (warp >= NN) return;
    int v = warp;

    // last-layer aggregation
    float2 acc = warp_gather_sum(v, lane);
    float d = g_dis[v];
    float2 b = *(const float2*)&bias[lane * 2];
    float hx = fmaxf(fmaf(d, acc.x, b.x), 0.f);
    float hy = fmaxf(fmaf(d, acc.y, b.y), 0.f);

    // jk final (registers only — no global write)
    float2 j = *(const float2*)&g_jk[(size_t)v * HD + lane * 2];
    float2 jv = make_float2(fmaxf(j.x, hx), fmaxf(j.y, hy));

    // projection: each active lane owns 2 output classes
    bool act = lane < 20;                   // 20 lanes x 2 cols = 40
    int c0 = lane * 2;
    float a0 = 0.f, a1 = 0.f;
    #pragma unroll
    for (int k = 0; k < HD; k++) {
        float hv = __shfl_sync(0xffffffffu, (k & 1) ? jv.y : jv.x, k >> 1);
        if (act) {
            float2 w = *(const float2*)&Wsm[k * CC + c0];
            a0 = fmaf(hv, w.x, a0);
            a1 = fmaf(hv, w.y, a1);
        }
    }
    if (act) { a0 += bsm[c0]; a1 += bsm[c0 + 1]; }

    float m = act ? fmaxf(a0, a1) : -INFINITY;
    #pragma unroll
    for (int off = 16; off; off >>= 1) m = fmaxf(m, __shfl_xor_sync(0xffffffffu, m, off));
    float s = act ? (expf(a0 - m) + expf(a1 - m)) : 0.f;
    #pragma unroll
    for (int off = 16; off; off >>= 1) s += __shfl_xor_sync(0xffffffffu, s, off);
    float lse = m + logf(s);

    if (act) {
        float2 o = make_float2(a0 - lse, a1 - lse);
        *(float2*)&out[(size_t)v * CC + c0] = o;
    }
}

// ---------------- launch ----------------
extern "C" void kernel_launch(void* const* d_in, const int* in_sizes, int n_in,
                              void* d_out, int out_size) {
    const float* x   = (const float*)d_in[0];
    const int*   ei  = (const int*)  d_in[1];
    const float* W0  = (const float*)d_in[2];
    const float* Ws  = (const float*)d_in[3];
    const float* bs  = (const float*)d_in[4];
    const float* fcw = (const float*)d_in[5];
    const float* fcb = (const float*)d_in[6];
    float* out = (float*)d_out;

    const int* src = ei;         // edge_index[0]
    const int* dst = ei + EE;    // edge_index[1]

    int* degp;
    cudaGetSymbolAddress((void**)&degp, g_deg);

    // CSR build (once per call, reused by all 6 layers)
    cudaMemsetAsync(degp, 0, NN * sizeof(int));
    k_count <<<(EE + 255) / 256, 256>>>(dst);
    k_scan1 <<<NB, 256>>>();
    k_scan2 <<<1, 512>>>();
    k_scan3 <<<NB, 256>>>();
    k_scatter<<<(EE + 255) / 256, 256>>>(src, dst);

    const int GEMM_GRID = (NN + 63) / 64;
    const int AGG_GRID  = (NN + 7) / 8;     // 8 warps per 256-thread block

    // layer 0: x (N x 128) @ W0
    k_gemm<FIN, true><<<GEMM_GRID, 256>>>(x, W0);
    k_agg<<<AGG_GRID, 256>>>(bs + 0 * HD, 1);

    // layers 1..4
    for (int l = 1; l < LL - 1; l++) {
        k_gemm<HD, false><<<GEMM_GRID, 256>>>(nullptr, Ws + (size_t)(l - 1) * HD * HD);
        k_agg<<<AGG_GRID, 256>>>(bs + (size_t)l * HD, 0);
    }
    // layer 5: aggregation fused with projection head
    k_gemm<HD, false><<<GEMM_GRID, 256>>>(nullptr, Ws + (size_t)(LL - 2) * HD * HD);
    k_agg_proj<<<AGG_GRID, 256>>>(bs + (size_t)(LL - 1) * HD, fcw, fcb, out);
}

// round 9
// speedup vs baseline: 1.7785x; 1.1153x over previous
#include <cuda_runtime.h>
#include <cuda_fp16.h>
#include <cstdint>
#include <math.h>

#define NN 100000
#define EE 1600000
#define FIN 128
#define HD  64
#define CC  40
#define LL  6
#define NB  ((NN + 255) / 256)   // 391 scan blocks

// ---------------- scratch (static device allocation; no cudaMalloc) ----------------
__device__ int   g_deg[NN];
__device__ int   g_rowptr[NN + 1];
__device__ int   g_fill[NN];
__device__ float g_dis[NN];
__device__ int   g_colidx[EE];
__device__ int   g_bsum[NB];
__device__ int   g_boff[NB];
__device__ float g_hn[(size_t)NN * HD];   // dis-scaled pre-aggregation features (fp32)
__device__ float g_h [(size_t)NN * HD];   // post-relu layer output
__device__ float g_jk[(size_t)NN * HD];   // running JumpingKnowledge max

// ---------------- graph preprocessing ----------------
__global__ void k_count(const int* __restrict__ dst) {
    int e = blockIdx.x * blockDim.x + threadIdx.x;
    if (e < EE) atomicAdd(&g_deg[dst[e]], 1);
}

__global__ void k_scan1() {
    __shared__ int wsum[8];
    int tid = threadIdx.x, lane = tid & 31, w = tid >> 5;
    int i = blockIdx.x * 256 + tid;
    int d = (i < NN) ? g_deg[i] : 0;
    int s = d;
    #pragma unroll
    for (int off = 16; off; off >>= 1) s += __shfl_xor_sync(0xffffffffu, s, off);
    if (lane == 0) wsum[w] = s;
    __syncthreads();
    if (tid == 0) {
        int t = 0;
        #pragma unroll
        for (int k = 0; k < 8; k++) t += wsum[k];
        g_bsum[blockIdx.x] = t;
    }
}

__global__ void k_scan2() {
    __shared__ int sh[512];
    int tid = threadIdx.x;
    int v = (tid < NB) ? g_bsum[tid] : 0;
    sh[tid] = v;
    __syncthreads();
    #pragma unroll
    for (int off = 1; off < 512; off <<= 1) {
        int t = (tid >= off) ? sh[tid - off] : 0;
        __syncthreads();
        sh[tid] += t;
        __syncthreads();
    }
    if (tid < NB) g_boff[tid] = sh[tid] - v;   // exclusive
    if (tid == 511) g_rowptr[NN] = sh[511];    // total == EE
}

__global__ void k_scan3() {
    __shared__ int wsum[8];
    __shared__ int woff[8];
    int tid = threadIdx.x, lane = tid & 31, w = tid >> 5;
    int i = blockIdx.x * 256 + tid;
    int d = (i < NN) ? g_deg[i] : 0;
    int x = d;
    #pragma unroll
    for (int off = 1; off < 32; off <<= 1) {
        int t = __shfl_up_sync(0xffffffffu, x, off);
        if (lane >= off) x += t;
    }
    if (lane == 31) wsum[w] = x;
    __syncthreads();
    if (w == 0 && lane < 8) {
        int v = wsum[lane];
        int y = v;
        #pragma unroll
        for (int off = 1; off < 8; off <<= 1) {
            int t = __shfl_up_sync(0xffu, y, off);
            if (lane >= off) y += t;
        }
        woff[lane] = y - v;   // exclusive over warps
    }
    __syncthreads();
    if (i < NN) {
        int excl = g_boff[blockIdx.x] + woff[w] + (x - d);
        g_rowptr[i] = excl;
        g_fill[i]   = excl;
        g_dis[i]    = rsqrtf((float)(d + 1));   // +1: self loop
    }
}

__global__ void k_scatter(const int* __restrict__ src, const int* __restrict__ dst) {
    int e = blockIdx.x * blockDim.x + threadIdx.x;
    if (e < EE) {
        int p = atomicAdd(&g_fill[dst[e]], 1);
        g_colidx[p] = src[e];
    }
}

// ---------------- tensor-core GEMM:  hn[row,:] = dis[row] * fp16(A[row,:]) @ fp16(W) ----------------
// 128x64 tile, 256 threads / 8 warps, warp w owns rows 16w..16w+15.
// mma.sync.m16n8k16 fp16 inputs, fp32 accum. hn output stays fp32.
__device__ __forceinline__ uint32_t smem_u32(const void* p) {
    return (uint32_t)__cvta_generic_to_shared(p);
}

#define AS_STRIDE 72
#define BS_STRIDE 72

template<int K, bool FROMX>
__global__ void k_gemm_mma(const float* __restrict__ Aext, const float* __restrict__ W) {
    __shared__ __half As[128][AS_STRIDE];
    __shared__ __half Bs[64][BS_STRIDE];
    const float* __restrict__ A = FROMX ? Aext : (const float*)g_h;

    int tid = threadIdx.x;
    int warp = tid >> 5, lane = tid & 31;
    int brow = blockIdx.x * 128;

    float d[8][4];
    #pragma unroll
    for (int i = 0; i < 8; i++)
        #pragma unroll
        for (int j = 0; j < 4; j++) d[i][j] = 0.f;

    for (int kc = 0; kc < K; kc += 64) {
        if (kc) __syncthreads();
        // stage A: 128 rows x 64 k, fp32 -> fp16. thread: row tid/2, halves (tid%2)*32..+31
        {
            int r = tid >> 1;
            int c0 = (tid & 1) * 32;
            int row = brow + r;
            #pragma unroll
            for (int i = 0; i < 2; i++) {       // two 16-half (32B) chunks
                __half2 h2[8];
                #pragma unroll
                for (int q = 0; q < 4; q++) {
                    float4 v = make_float4(0.f, 0.f, 0.f, 0.f);
                    if (row < NN)
                        v = *(const float4*)&A[(size_t)row * K + kc + c0 + i * 16 + q * 4];
                    h2[q * 2 + 0] = __floats2half2_rn(v.x, v.y);
                    h2[q * 2 + 1] = __floats2half2_rn(v.z, v.w);
                }
                #pragma unroll
                for (int q = 0; q < 4; q++) {
                    uint2 pk;
                    pk.x = *(unsigned int*)&h2[q * 2 + 0];
                    pk.y = *(unsigned int*)&h2[q * 2 + 1];
                    *(uint2*)&As[r][c0 + i * 16 + q * 4] = pk;
                }
            }
        }
        // stage B: 64 k-rows x 64 cols. thread: row tid/4, cols (tid%4)*16..+15
        {
            int r = tid >> 2;
            int c0 = (tid & 3) * 16;
            #pragma unroll
            for (int q = 0; q < 4; q++) {
                float4 v = *(const float4*)&W[(size_t)(kc + r) * HD + c0 + q * 4];
                __half2 p0 = __floats2half2_rn(v.x, v.y);
                __half2 p1 = __floats2half2_rn(v.z, v.w);
                uint2 pk;
                pk.x = *(unsigned int*)&p0;
                pk.y = *(unsigned int*)&p1;
                *(uint2*)&Bs[r][c0 + q * 4] = pk;
            }
        }
        __syncthreads();

        // mainloop: 4 k-steps of 16
        #pragma unroll
        for (int kk = 0; kk < 4; kk++) {
            uint32_t a0, a1, a2, a3;
            {
                int j = lane >> 3;
                uint32_t addr = smem_u32(&As[warp * 16 + (lane & 7) + 8 * (j & 1)]
                                            [kk * 16 + 8 * (j >> 1)]);
                asm volatile("ldmatrix.sync.aligned.m8n8.x4.shared.b16 {%0,%1,%2,%3}, [%4];"
                             : "=r"(a0), "=r"(a1), "=r"(a2), "=r"(a3) : "r"(addr));
            }
            #pragma unroll
            for (int nt = 0; nt < 8; nt += 2) {
                uint32_t b0, b1, b2, b3;
                int j = lane >> 3;
                uint32_t addr = smem_u32(&Bs[kk * 16 + (lane & 7) + 8 * (j & 1)]
                                            [nt * 8 + 8 * (j >> 1)]);
                asm volatile("ldmatrix.sync.aligned.m8n8.x4.trans.shared.b16 {%0,%1,%2,%3}, [%4];"
                             : "=r"(b0), "=r"(b1), "=r"(b2), "=r"(b3) : "r"(addr));
                asm volatile("mma.sync.aligned.m16n8k16.row.col.f32.f16.f16.f32 "
                             "{%0,%1,%2,%3}, {%4,%5,%6,%7}, {%8,%9}, {%0,%1,%2,%3};"
                             : "+f"(d[nt][0]), "+f"(d[nt][1]), "+f"(d[nt][2]), "+f"(d[nt][3])
                             : "r"(a0), "r"(a1), "r"(a2), "r"(a3), "r"(b0), "r"(b1));
                asm volatile("mma.sync.aligned.m16n8k16.row.col.f32.f16.f16.f32 "
                             "{%0,%1,%2,%3}, {%4,%5,%6,%7}, {%8,%9}, {%0,%1,%2,%3};"
                             : "+f"(d[nt+1][0]), "+f"(d[nt+1][1]), "+f"(d[nt+1][2]), "+f"(d[nt+1][3])
                             : "r"(a0), "r"(a1), "r"(a2), "r"(a3), "r"(b2), "r"(b3));
            }
        }
    }

    // epilogue: thread owns rows (g, g+8) of warp tile, cols 2q within each n8 tile
    int g = lane >> 2, q = lane & 3;
    int row0 = brow + warp * 16 + g;
    int row1 = row0 + 8;
    float d0 = (row0 < NN) ? g_dis[row0] : 0.f;
    float d1 = (row1 < NN) ? g_dis[row1] : 0.f;
    #pragma unroll
    for (int nt = 0; nt < 8; nt++) {
        int c = nt * 8 + 2 * q;
        if (row0 < NN)
            *(float2*)&g_hn[(size_t)row0 * HD + c] = make_float2(d[nt][0] * d0, d[nt][1] * d0);
        if (row1 < NN)
            *(float2*)&g_hn[(size_t)row1 * HD + c] = make_float2(d[nt][2] * d1, d[nt][3] * d1);
    }
}

// ---------------- R1 gather: warp per node, scalar uniform colidx, 4-wide ----------------
__device__ __forceinline__ float2 warp_gather_sum(int v, int lane) {
    int beg = g_rowptr[v], end = g_rowptr[v + 1];
    size_t fo = (size_t)v * HD + lane * 2;
    float2 acc = *(const float2*)&g_hn[fo];   // self-loop term

    int p = beg;
    for (; p + 4 <= end; p += 4) {
        int u0 = g_colidx[p + 0];
        int u1 = g_colidx[p + 1];
        int u2 = g_colidx[p + 2];
        int u3 = g_colidx[p + 3];
        float2 t0 = *(const float2*)&g_hn[(size_t)u0 * HD + lane * 2];
        float2 t1 = *(const float2*)&g_hn[(size_t)u1 * HD + lane * 2];
        float2 t2 = *(const float2*)&g_hn[(size_t)u2 * HD + lane * 2];
        float2 t3 = *(const float2*)&g_hn[(size_t)u3 * HD + lane * 2];
        acc.x += (t0.x + t1.x) + (t2.x + t3.x);
        acc.y += (t0.y + t1.y) + (t2.y + t3.y);
    }
    for (; p < end; p++) {
        int u = g_colidx[p];
        float2 t = *(const float2*)&g_hn[(size_t)u * HD + lane * 2];
        acc.x += t.x; acc.y += t.y;
    }
    return acc;
}

__global__ void k_agg(const float* __restrict__ bias, int first) {
    int warp = (blockIdx.x * blockDim.x + threadIdx.x) >> 5;
    int lane = threadIdx.x & 31;
    if (warp >= NN) return;
    int v = warp;

    float2 acc = warp_gather_sum(v, lane);
    float d = g_dis[v];
    float2 b = *(const float2*)&bias[lane * 2];
    float hx = fmaxf(fmaf(d, acc.x, b.x), 0.f);
    float hy = fmaxf(fmaf(d, acc.y, b.y), 0.f);

    size_t fo = (size_t)v * HD + lane * 2;
    *(float2*)&g_h[fo] = make_float2(hx, hy);
    if (first) {
        *(float2*)&g_jk[fo] = make_float2(hx, hy);
    } else {
        float2 j = *(const float2*)&g_jk[fo];
        *(float2*)&g_jk[fo] = make_float2(fmaxf(j.x, hx), fmaxf(j.y, hy));
    }
}

// ---------------- last layer fused with head: agg -> jk-final (regs) -> proj -> log_softmax ----------------
__global__ void k_agg_proj(const float* __restrict__ bias,
                           const float* __restrict__ fcw, const float* __restrict__ fcb,
                           float* __restrict__ out) {
    __shared__ float Wsm[HD * CC];
    __shared__ float bsm[CC];
    int tid = threadIdx.x;
    for (int i = tid; i < HD * CC; i += blockDim.x) Wsm[i] = fcw[i];
    if (tid < CC) bsm[tid] = fcb[tid];
    __syncthreads();

    int warp = (blockIdx.x * blockDim.x + tid) >> 5;
    int lane = tid & 31;
    if (warp >= NN) return;
    int v = warp;

    float2 acc = warp_gather_sum(v, lane);
    float d = g_dis[v];
    float2 b = *(const float2*)&bias[lane * 2];
    float hx = fmaxf(fmaf(d, acc.x, b.x), 0.f);
    float hy = fmaxf(fmaf(d, acc.y, b.y), 0.f);

    float2 j = *(const float2*)&g_jk[(size_t)v * HD + lane * 2];
    float2 jv = make_float2(fmaxf(j.x, hx), fmaxf(j.y, hy));

    bool act = lane < 20;                   // 20 lanes x 2 cols = 40
    int c0 = lane * 2;
    float a0 = 0.f, a1 = 0.f;
    #pragma unroll
    for (int k = 0; k < HD; k++) {
        float hv = __shfl_sync(0xffffffffu, (k & 1) ? jv.y : jv.x, k >> 1);
        if (act) {
            float2 w = *(const float2*)&Wsm[k * CC + c0];
            a0 = fmaf(hv, w.x, a0);
            a1 = fmaf(hv, w.y, a1);
        }
    }
    if (act) { a0 += bsm[c0]; a1 += bsm[c0 + 1]; }

    float m = act ? fmaxf(a0, a1) : -INFINITY;
    #pragma unroll
    for (int off = 16; off; off >>= 1) m = fmaxf(m, __shfl_xor_sync(0xffffffffu, m, off));
    float s = act ? (expf(a0 - m) + expf(a1 - m)) : 0.f;
    #pragma unroll
    for (int off = 16; off; off >>= 1) s += __shfl_xor_sync(0xffffffffu, s, off);
    float lse = m + logf(s);

    if (act) {
        float2 o = make_float2(a0 - lse, a1 - lse);
        *(float2*)&out[(size_t)v * CC + c0] = o;
    }
}

// ---------------- launch ----------------
extern "C" void kernel_launch(void* const* d_in, const int* in_sizes, int n_in,
                              void* d_out, int out_size) {
    const float* x   = (const float*)d_in[0];
    const int*   ei  = (const int*)  d_in[1];
    const float* W0  = (const float*)d_in[2];
    const float* Ws  = (const float*)d_in[3];
    const float* bs  = (const float*)d_in[4];
    const float* fcw = (const float*)d_in[5];
    const float* fcb = (const float*)d_in[6];
    float* out = (float*)d_out;

    const int* src = ei;         // edge_index[0]
    const int* dst = ei + EE;    // edge_index[1]

    int* degp;
    cudaGetSymbolAddress((void**)&degp, g_deg);

    // CSR build (once per call, reused by all 6 layers)
    cudaMemsetAsync(degp, 0, NN * sizeof(int));
    k_count <<<(EE + 255) / 256, 256>>>(dst);
    k_scan1 <<<NB, 256>>>();
    k_scan2 <<<1, 512>>>();
    k_scan3 <<<NB, 256>>>();
    k_scatter<<<(EE + 255) / 256, 256>>>(src, dst);

    const int GEMM_GRID = (NN + 127) / 128;  // 782 (128-row tiles)
    const int AGG_GRID  = (NN + 7) / 8;      // 8 warps per 256-thread block

    // layer 0: x (N x 128) @ W0
    k_gemm_mma<FIN, true><<<GEMM_GRID, 256>>>(x, W0);
    k_agg<<<AGG_GRID, 256>>>(bs + 0 * HD, 1);

    // layers 1..4
    for (int l = 1; l < LL - 1; l++) {
        k_gemm_mma<HD, false><<<GEMM_GRID, 256>>>(nullptr, Ws + (size_t)(l - 1) * HD * HD);
        k_agg<<<AGG_GRID, 256>>>(bs + (size_t)l * HD, 0);
    }
    // layer 5: aggregation fused with projection head
    k_gemm_mma<HD, false><<<GEMM_GRID, 256>>>(nullptr, Ws + (size_t)(LL - 2) * HD * HD);
    k_agg_proj<<<AGG_GRID, 256>>>(bs + (size_t)(LL - 1) * HD, fcw, fcb, out);
}

// round 10
// speedup vs baseline: 1.9356x; 1.0883x over previous
#include <cuda_runtime.h>
#include <cuda_fp16.h>
#include <cstdint>
#include <math.h>

#define NN 100000
#define EE 1600000
#define FIN 128
#define HD  64
#define CC  40
#define LL  6
#define NB  ((NN + 255) / 256)   // 391 scan blocks

// ---------------- scratch (static device allocation; no cudaMalloc) ----------------
__device__ int    g_deg[NN];
__device__ int    g_rowptr[NN + 1];
__device__ int    g_fill[NN];
__device__ float  g_dis[NN];
__device__ int    g_colidx[EE];
__device__ int    g_bsum[NB];
__device__ int    g_boff[NB];
__device__ float  g_hn[(size_t)NN * HD];   // dis-scaled pre-aggregation features (fp32)
__device__ __half g_h16[(size_t)NN * HD];  // post-relu layer output (fp16 == GEMM A operand)
__device__ float  g_jk[(size_t)NN * HD];   // running JumpingKnowledge max (fp32)

// ---------------- graph preprocessing ----------------
__global__ void k_count(const int* __restrict__ dst) {
    int e = blockIdx.x * blockDim.x + threadIdx.x;
    if (e < EE) atomicAdd(&g_deg[dst[e]], 1);
}

__global__ void k_scan1() {
    __shared__ int wsum[8];
    int tid = threadIdx.x, lane = tid & 31, w = tid >> 5;
    int i = blockIdx.x * 256 + tid;
    int d = (i < NN) ? g_deg[i] : 0;
    int s = d;
    #pragma unroll
    for (int off = 16; off; off >>= 1) s += __shfl_xor_sync(0xffffffffu, s, off);
    if (lane == 0) wsum[w] = s;
    __syncthreads();
    if (tid == 0) {
        int t = 0;
        #pragma unroll
        for (int k = 0; k < 8; k++) t += wsum[k];
        g_bsum[blockIdx.x] = t;
    }
}

__global__ void k_scan2() {
    __shared__ int sh[512];
    int tid = threadIdx.x;
    int v = (tid < NB) ? g_bsum[tid] : 0;
    sh[tid] = v;
    __syncthreads();
    #pragma unroll
    for (int off = 1; off < 512; off <<= 1) {
        int t = (tid >= off) ? sh[tid - off] : 0;
        __syncthreads();
        sh[tid] += t;
        __syncthreads();
    }
    if (tid < NB) g_boff[tid] = sh[tid] - v;   // exclusive
    if (tid == 511) g_rowptr[NN] = sh[511];    // total == EE
}

__global__ void k_scan3() {
    __shared__ int wsum[8];
    __shared__ int woff[8];
    int tid = threadIdx.x, lane = tid & 31, w = tid >> 5;
    int i = blockIdx.x * 256 + tid;
    int d = (i < NN) ? g_deg[i] : 0;
    int x = d;
    #pragma unroll
    for (int off = 1; off < 32; off <<= 1) {
        int t = __shfl_up_sync(0xffffffffu, x, off);
        if (lane >= off) x += t;
    }
    if (lane == 31) wsum[w] = x;
    __syncthreads();
    if (w == 0 && lane < 8) {
        int v = wsum[lane];
        int y = v;
        #pragma unroll
        for (int off = 1; off < 8; off <<= 1) {
            int t = __shfl_up_sync(0xffu, y, off);
            if (lane >= off) y += t;
        }
        woff[lane] = y - v;   // exclusive over warps
    }
    __syncthreads();
    if (i < NN) {
        int excl = g_boff[blockIdx.x] + woff[w] + (x - d);
        g_rowptr[i] = excl;
        g_fill[i]   = excl;
        g_dis[i]    = rsqrtf((float)(d + 1));   // +1: self loop
    }
}

__global__ void k_scatter(const int* __restrict__ src, const int* __restrict__ dst) {
    int e = blockIdx.x * blockDim.x + threadIdx.x;
    if (e < EE) {
        int p = atomicAdd(&g_fill[dst[e]], 1);
        g_colidx[p] = src[e];
    }
}

// ---------------- tensor-core GEMM:  hn[row,:] = dis[row] * fp16(A[row,:]) @ fp16(W) ----------------
// 128x64 tile, 256 threads / 8 warps, warp w owns rows 16w..16w+15.
__device__ __forceinline__ uint32_t smem_u32(const void* p) {
    return (uint32_t)__cvta_generic_to_shared(p);
}

#define AS_STRIDE 72
#define BS_STRIDE 72

template<int K, bool FROMX>
__global__ void k_gemm_mma(const float* __restrict__ Aext, const float* __restrict__ W) {
    __shared__ __half As[128][AS_STRIDE];
    __shared__ __half Bs[64][BS_STRIDE];

    int tid = threadIdx.x;
    int warp = tid >> 5, lane = tid & 31;
    int brow = blockIdx.x * 128;

    float d[8][4];
    #pragma unroll
    for (int i = 0; i < 8; i++)
        #pragma unroll
        for (int j = 0; j < 4; j++) d[i][j] = 0.f;

    for (int kc = 0; kc < K; kc += 64) {
        if (kc) __syncthreads();
        // stage A: 128 rows x 64 k. thread: row tid/2, halves (tid%2)*32..+31
        {
            int r = tid >> 1;
            int c0 = (tid & 1) * 32;
            int row = brow + r;
            if (FROMX) {
                // fp32 source -> convert
                #pragma unroll
                for (int i = 0; i < 8; i++) {
                    float4 v = make_float4(0.f, 0.f, 0.f, 0.f);
                    if (row < NN)
                        v = *(const float4*)&Aext[(size_t)row * K + kc + c0 + i * 4];
                    __half2 p0 = __floats2half2_rn(v.x, v.y);
                    __half2 p1 = __floats2half2_rn(v.z, v.w);
                    uint2 pk;
                    pk.x = *(unsigned int*)&p0;
                    pk.y = *(unsigned int*)&p1;
                    *(uint2*)&As[r][c0 + i * 4] = pk;
                }
            } else {
                // fp16 source (g_h16) -> straight copy, 32 halves = 4 x uint4
                #pragma unroll
                for (int i = 0; i < 4; i++) {
                    uint4 v = make_uint4(0, 0, 0, 0);
                    if (row < NN)
                        v = *(const uint4*)&g_h16[(size_t)row * K + kc + c0 + i * 8];
                    *(uint4*)&As[r][c0 + i * 8] = v;
                }
            }
        }
        // stage B: 64 k-rows x 64 cols. thread: row tid/4, cols (tid%4)*16..+15
        {
            int r = tid >> 2;
            int c0 = (tid & 3) * 16;
            #pragma unroll
            for (int q = 0; q < 4; q++) {
                float4 v = *(const float4*)&W[(size_t)(kc + r) * HD + c0 + q * 4];
                __half2 p0 = __floats2half2_rn(v.x, v.y);
                __half2 p1 = __floats2half2_rn(v.z, v.w);
                uint2 pk;
                pk.x = *(unsigned int*)&p0;
                pk.y = *(unsigned int*)&p1;
                *(uint2*)&Bs[r][c0 + q * 4] = pk;
            }
        }
        __syncthreads();

        // mainloop: 4 k-steps of 16
        #pragma unroll
        for (int kk = 0; kk < 4; kk++) {
            uint32_t a0, a1, a2, a3;
            {
                int j = lane >> 3;
                uint32_t addr = smem_u32(&As[warp * 16 + (lane & 7) + 8 * (j & 1)]
                                            [kk * 16 + 8 * (j >> 1)]);
                asm volatile("ldmatrix.sync.aligned.m8n8.x4.shared.b16 {%0,%1,%2,%3}, [%4];"
                             : "=r"(a0), "=r"(a1), "=r"(a2), "=r"(a3) : "r"(addr));
            }
            #pragma unroll
            for (int nt = 0; nt < 8; nt += 2) {
                uint32_t b0, b1, b2, b3;
                int j = lane >> 3;
                uint32_t addr = smem_u32(&Bs[kk * 16 + (lane & 7) + 8 * (j & 1)]
                                            [nt * 8 + 8 * (j >> 1)]);
                asm volatile("ldmatrix.sync.aligned.m8n8.x4.trans.shared.b16 {%0,%1,%2,%3}, [%4];"
                             : "=r"(b0), "=r"(b1), "=r"(b2), "=r"(b3) : "r"(addr));
                asm volatile("mma.sync.aligned.m16n8k16.row.col.f32.f16.f16.f32 "
                             "{%0,%1,%2,%3}, {%4,%5,%6,%7}, {%8,%9}, {%0,%1,%2,%3};"
                             : "+f"(d[nt][0]), "+f"(d[nt][1]), "+f"(d[nt][2]), "+f"(d[nt][3])
                             : "r"(a0), "r"(a1), "r"(a2), "r"(a3), "r"(b0), "r"(b1));
                asm volatile("mma.sync.aligned.m16n8k16.row.col.f32.f16.f16.f32 "
                             "{%0,%1,%2,%3}, {%4,%5,%6,%7}, {%8,%9}, {%0,%1,%2,%3};"
                             : "+f"(d[nt+1][0]), "+f"(d[nt+1][1]), "+f"(d[nt+1][2]), "+f"(d[nt+1][3])
                             : "r"(a0), "r"(a1), "r"(a2), "r"(a3), "r"(b2), "r"(b3));
            }
        }
    }

    // epilogue: thread owns rows (g, g+8) of warp tile, cols 2q within each n8 tile
    int g = lane >> 2, q = lane & 3;
    int row0 = brow + warp * 16 + g;
    int row1 = row0 + 8;
    float d0 = (row0 < NN) ? g_dis[row0] : 0.f;
    float d1 = (row1 < NN) ? g_dis[row1] : 0.f;
    #pragma unroll
    for (int nt = 0; nt < 8; nt++) {
        int c = nt * 8 + 2 * q;
        if (row0 < NN)
            *(float2*)&g_hn[(size_t)row0 * HD + c] = make_float2(d[nt][0] * d0, d[nt][1] * d0);
        if (row1 < NN)
            *(float2*)&g_hn[(size_t)row1 * HD + c] = make_float2(d[nt][2] * d1, d[nt][3] * d1);
    }
}

// ---------------- gather: warp per node, software-pipelined colidx, 4-wide gathers ----------------
__device__ __forceinline__ float2 warp_gather_sum(int v, int lane) {
    int beg = g_rowptr[v], end = g_rowptr[v + 1];
    size_t fo = (size_t)v * HD + lane * 2;
    float2 acc = *(const float2*)&g_hn[fo];   // self-loop term

    int p = beg;
    if (p + 4 <= end) {
        int c0 = g_colidx[p + 0];
        int c1 = g_colidx[p + 1];
        int c2 = g_colidx[p + 2];
        int c3 = g_colidx[p + 3];
        for (; p + 8 <= end; p += 4) {
            int n0 = g_colidx[p + 4];
            int n1 = g_colidx[p + 5];
            int n2 = g_colidx[p + 6];
            int n3 = g_colidx[p + 7];
            float2 t0 = *(const float2*)&g_hn[(size_t)c0 * HD + lane * 2];
            float2 t1 = *(const float2*)&g_hn[(size_t)c1 * HD + lane * 2];
            float2 t2 = *(const float2*)&g_hn[(size_t)c2 * HD + lane * 2];
            float2 t3 = *(const float2*)&g_hn[(size_t)c3 * HD + lane * 2];
            acc.x += (t0.x + t1.x) + (t2.x + t3.x);
            acc.y += (t0.y + t1.y) + (t2.y + t3.y);
            c0 = n0; c1 = n1; c2 = n2; c3 = n3;
        }
        float2 t0 = *(const float2*)&g_hn[(size_t)c0 * HD + lane * 2];
        float2 t1 = *(const float2*)&g_hn[(size_t)c1 * HD + lane * 2];
        float2 t2 = *(const float2*)&g_hn[(size_t)c2 * HD + lane * 2];
        float2 t3 = *(const float2*)&g_hn[(size_t)c3 * HD + lane * 2];
        acc.x += (t0.x + t1.x) + (t2.x + t3.x);
        acc.y += (t0.y + t1.y) + (t2.y + t3.y);
        p += 4;
    }
    for (; p < end; p++) {
        int u = g_colidx[p];
        float2 t = *(const float2*)&g_hn[(size_t)u * HD + lane * 2];
        acc.x += t.x; acc.y += t.y;
    }
    return acc;
}

__global__ void __launch_bounds__(256, 8)
k_agg(const float* __restrict__ bias, int first) {
    int warp = (blockIdx.x * blockDim.x + threadIdx.x) >> 5;
    int lane = threadIdx.x & 31;
    if (warp >= NN) return;
    int v = warp;

    float2 acc = warp_gather_sum(v, lane);
    float d = g_dis[v];
    float2 b = *(const float2*)&bias[lane * 2];
    float hx = fmaxf(fmaf(d, acc.x, b.x), 0.f);
    float hy = fmaxf(fmaf(d, acc.y, b.y), 0.f);

    size_t fo = (size_t)v * HD + lane * 2;
    __half2 h16 = __floats2half2_rn(hx, hy);   // same RN rounding the GEMM would apply
    *(__half2*)&g_h16[fo] = h16;
    if (first) {
        *(float2*)&g_jk[fo] = make_float2(hx, hy);
    } else {
        float2 j = *(const float2*)&g_jk[fo];
        *(float2*)&g_jk[fo] = make_float2(fmaxf(j.x, hx), fmaxf(j.y, hy));
    }
}

// ---------------- last layer fused with head: agg -> jk-final (regs) -> proj -> log_softmax ----------------
__global__ void __launch_bounds__(256, 8)
k_agg_proj(const float* __restrict__ bias,
           const float* __restrict__ fcw, const float* __restrict__ fcb,
           float* __restrict__ out) {
    __shared__ float Wsm[HD * CC];
    __shared__ float bsm[CC];
    int tid = threadIdx.x;
    for (int i = tid; i < HD * CC; i += blockDim.x) Wsm[i] = fcw[i];
    if (tid < CC) bsm[tid] = fcb[tid];
    __syncthreads();

    int warp = (blockIdx.x * blockDim.x + tid) >> 5;
    int lane = tid & 31;
    if (warp >= NN) return;
    int v = warp;

    float2 acc = warp_gather_sum(v, lane);
    float d = g_dis[v];
    float2 b = *(const float2*)&bias[lane * 2];
    float hx = fmaxf(fmaf(d, acc.x, b.x), 0.f);
    float hy = fmaxf(fmaf(d, acc.y, b.y), 0.f);

    float2 j = *(const float2*)&g_jk[(size_t)v * HD + lane * 2];
    float2 jv = make_float2(fmaxf(j.x, hx), fmaxf(j.y, hy));

    bool act = lane < 20;                   // 20 lanes x 2 cols = 40
    int c0 = lane * 2;
    float a0 = 0.f, a1 = 0.f;
    #pragma unroll
    for (int k = 0; k < HD; k++) {
        float hv = __shfl_sync(0xffffffffu, (k & 1) ? jv.y : jv.x, k >> 1);
        if (act) {
            float2 w = *(const float2*)&Wsm[k * CC + c0];
            a0 = fmaf(hv, w.x, a0);
            a1 = fmaf(hv, w.y, a1);
        }
    }
    if (act) { a0 += bsm[c0]; a1 += bsm[c0 + 1]; }

    float m = act ? fmaxf(a0, a1) : -INFINITY;
    #pragma unroll
    for (int off = 16; off; off >>= 1) m = fmaxf(m, __shfl_xor_sync(0xffffffffu, m, off));
    float s = act ? (expf(a0 - m) + expf(a1 - m)) : 0.f;
    #pragma unroll
    for (int off = 16; off; off >>= 1) s += __shfl_xor_sync(0xffffffffu, s, off);
    float lse = m + logf(s);

    if (act) {
        float2 o = make_float2(a0 - lse, a1 - lse);
        *(float2*)&out[(size_t)v * CC + c0] = o;
    }
}

// ---------------- launch ----------------
extern "C" void kernel_launch(void* const* d_in, const int* in_sizes, int n_in,
                              void* d_out, int out_size) {
    const float* x   = (const float*)d_in[0];
    const int*   ei  = (const int*)  d_in[1];
    const float* W0  = (const float*)d_in[2];
    const float* Ws  = (const float*)d_in[3];
    const float* bs  = (const float*)d_in[4];
    const float* fcw = (const float*)d_in[5];
    const float* fcb = (const float*)d_in[6];
    float* out = (float*)d_out;

    const int* src = ei;         // edge_index[0]
    const int* dst = ei + EE;    // edge_index[1]

    int* degp;
    cudaGetSymbolAddress((void**)&degp, g_deg);

    // CSR build (once per call, reused by all 6 layers)
    cudaMemsetAsync(degp, 0, NN * sizeof(int));
    k_count <<<(EE + 255) / 256, 256>>>(dst);
    k_scan1 <<<NB, 256>>>();
    k_scan2 <<<1, 512>>>();
    k_scan3 <<<NB, 256>>>();
    k_scatter<<<(EE + 255) / 256, 256>>>(src, dst);

    const int GEMM_GRID = (NN + 127) / 128;  // 782 (128-row tiles)
    const int AGG_GRID  = (NN + 7) / 8;      // 8 warps per 256-thread block

    // layer 0: x (N x 128) @ W0
    k_gemm_mma<FIN, true><<<GEMM_GRID, 256>>>(x, W0);
    k_agg<<<AGG_GRID, 256>>>(bs + 0 * HD, 1);

    // layers 1..4
    for (int l = 1; l < LL - 1; l++) {
        k_gemm_mma<HD, false><<<GEMM_GRID, 256>>>(nullptr, Ws + (size_t)(l - 1) * HD * HD);
        k_agg<<<AGG_GRID, 256>>>(bs + (size_t)l * HD, 0);
    }
    // layer 5: aggregation fused with projection head
    k_gemm_mma<HD, false><<<GEMM_GRID, 256>>>(nullptr, Ws + (size_t)(LL - 2) * HD * HD);
    k_agg_proj<<<AGG_GRID, 256>>>(bs + (size_t)(LL - 1) * HD, fcw, fcb, out);
}

// round 11
// speedup vs baseline: 1.9509x; 1.0079x over previous
#include <cuda_runtime.h>
#include <cuda_fp16.h>
#include <cstdint>
#include <math.h>

#define NN 100000
#define EE 1600000
#define FIN 128
#define HD  64
#define CC  40
#define LL  6
#define NB  ((NN + 255) / 256)       // 391 scan blocks
#define CIMAX (EE + 3 * NN)          // padded colidx capacity

// ---------------- scratch (static device allocation; no cudaMalloc) ----------------
__device__ int    g_deg[NN];
__device__ int    g_rowptr[NN + 1];  // PADDED offsets (each node multiple of 4)
__device__ int    g_fill[NN];
__device__ float  g_dis[NN];
__device__ int    g_colidx[CIMAX];
__device__ int    g_bsum[NB];
__device__ int    g_boff[NB];
__device__ float  g_hn[(size_t)(NN + 1) * HD]; // +1: sentinel zero row (index NN)
__device__ __half g_h16[(size_t)NN * HD];      // post-relu layer output (fp16 GEMM A)
__device__ float  g_jk[(size_t)NN * HD];       // running JumpingKnowledge max (fp32)

// ---------------- graph preprocessing ----------------
__global__ void k_count(const int* __restrict__ dst) {
    int e4 = (blockIdx.x * blockDim.x + threadIdx.x) * 4;
    if (e4 < EE) {
        int4 d = *(const int4*)&dst[e4];
        atomicAdd(&g_deg[d.x], 1);
        atomicAdd(&g_deg[d.y], 1);
        atomicAdd(&g_deg[d.z], 1);
        atomicAdd(&g_deg[d.w], 1);
    }
}

__global__ void k_scan1() {
    __shared__ int wsum[8];
    int tid = threadIdx.x, lane = tid & 31, w = tid >> 5;
    int i = blockIdx.x * 256 + tid;
    int pd = (i < NN) ? ((g_deg[i] + 3) & ~3) : 0;   // padded degree
    int s = pd;
    #pragma unroll
    for (int off = 16; off; off >>= 1) s += __shfl_xor_sync(0xffffffffu, s, off);
    if (lane == 0) wsum[w] = s;
    __syncthreads();
    if (tid == 0) {
        int t = 0;
        #pragma unroll
        for (int k = 0; k < 8; k++) t += wsum[k];
        g_bsum[blockIdx.x] = t;
    }
}

__global__ void k_scan2() {
    __shared__ int sh[512];
    int tid = threadIdx.x;
    int v = (tid < NB) ? g_bsum[tid] : 0;
    sh[tid] = v;
    __syncthreads();
    #pragma unroll
    for (int off = 1; off < 512; off <<= 1) {
        int t = (tid >= off) ? sh[tid - off] : 0;
        __syncthreads();
        sh[tid] += t;
        __syncthreads();
    }
    if (tid < NB) g_boff[tid] = sh[tid] - v;   // exclusive
    if (tid == 511) g_rowptr[NN] = sh[511];    // total padded count
}

__global__ void k_scan3() {
    __shared__ int wsum[8];
    __shared__ int woff[8];
    int tid = threadIdx.x, lane = tid & 31, w = tid >> 5;
    int i = blockIdx.x * 256 + tid;
    int d  = (i < NN) ? g_deg[i] : 0;
    int pd = (d + 3) & ~3;
    int x = pd;
    #pragma unroll
    for (int off = 1; off < 32; off <<= 1) {
        int t = __shfl_up_sync(0xffffffffu, x, off);
        if (lane >= off) x += t;
    }
    if (lane == 31) wsum[w] = x;
    __syncthreads();
    if (w == 0 && lane < 8) {
        int v = wsum[lane];
        int y = v;
        #pragma unroll
        for (int off = 1; off < 8; off <<= 1) {
            int t = __shfl_up_sync(0xffu, y, off);
            if (lane >= off) y += t;
        }
        woff[lane] = y - v;   // exclusive over warps
    }
    __syncthreads();
    if (i < NN) {
        int excl = g_boff[blockIdx.x] + woff[w] + (x - pd);
        g_rowptr[i] = excl;
        g_fill[i]   = excl;
        g_dis[i]    = rsqrtf((float)(d + 1));   // +1: self loop
    }
}

__global__ void k_scatter(const int* __restrict__ src, const int* __restrict__ dst) {
    int e4 = (blockIdx.x * blockDim.x + threadIdx.x) * 4;
    if (e4 < EE) {
        int4 s = *(const int4*)&src[e4];
        int4 d = *(const int4*)&dst[e4];
        int p;
        p = atomicAdd(&g_fill[d.x], 1); g_colidx[p] = s.x;
        p = atomicAdd(&g_fill[d.y], 1); g_colidx[p] = s.y;
        p = atomicAdd(&g_fill[d.z], 1); g_colidx[p] = s.z;
        p = atomicAdd(&g_fill[d.w], 1); g_colidx[p] = s.w;
    }
}

// pad each node's edge list to its padded length with sentinel NN; zero sentinel hn row
__global__ void k_pad() {
    int i = blockIdx.x * 256 + threadIdx.x;
    if (i < NN) {
        int e = g_fill[i];           // rowptr[i] + deg[i]
        int pe = g_rowptr[i + 1];    // padded end (contiguous: next node's start)
        for (int p = e; p < pe; p++) g_colidx[p] = NN;
    }
    if (blockIdx.x == 0 && threadIdx.x < HD)
        g_hn[(size_t)NN * HD + threadIdx.x] = 0.f;
}

// ---------------- tensor-core GEMM:  hn[row,:] = dis[row] * fp16(A[row,:]) @ fp16(W) ----------------
__device__ __forceinline__ uint32_t smem_u32(const void* p) {
    return (uint32_t)__cvta_generic_to_shared(p);
}

#define AS_STRIDE 72
#define BS_STRIDE 72

template<int K, bool FROMX>
__global__ void k_gemm_mma(const float* __restrict__ Aext, const float* __restrict__ W) {
    __shared__ __half As[128][AS_STRIDE];
    __shared__ __half Bs[64][BS_STRIDE];

    int tid = threadIdx.x;
    int warp = tid >> 5, lane = tid & 31;
    int brow = blockIdx.x * 128;

    float d[8][4];
    #pragma unroll
    for (int i = 0; i < 8; i++)
        #pragma unroll
        for (int j = 0; j < 4; j++) d[i][j] = 0.f;

    for (int kc = 0; kc < K; kc += 64) {
        if (kc) __syncthreads();
        {
            int r = tid >> 1;
            int c0 = (tid & 1) * 32;
            int row = brow + r;
            if (FROMX) {
                #pragma unroll
                for (int i = 0; i < 8; i++) {
                    float4 v = make_float4(0.f, 0.f, 0.f, 0.f);
                    if (row < NN)
                        v = *(const float4*)&Aext[(size_t)row * K + kc + c0 + i * 4];
                    __half2 p0 = __floats2half2_rn(v.x, v.y);
                    __half2 p1 = __floats2half2_rn(v.z, v.w);
                    uint2 pk;
                    pk.x = *(unsigned int*)&p0;
                    pk.y = *(unsigned int*)&p1;
                    *(uint2*)&As[r][c0 + i * 4] = pk;
                }
            } else {
                #pragma unroll
                for (int i = 0; i < 4; i++) {
                    uint4 v = make_uint4(0, 0, 0, 0);
                    if (row < NN)
                        v = *(const uint4*)&g_h16[(size_t)row * K + kc + c0 + i * 8];
                    *(uint4*)&As[r][c0 + i * 8] = v;
                }
            }
        }
        {
            int r = tid >> 2;
            int c0 = (tid & 3) * 16;
            #pragma unroll
            for (int q = 0; q < 4; q++) {
                float4 v = *(const float4*)&W[(size_t)(kc + r) * HD + c0 + q * 4];
                __half2 p0 = __floats2half2_rn(v.x, v.y);
                __half2 p1 = __floats2half2_rn(v.z, v.w);
                uint2 pk;
                pk.x = *(unsigned int*)&p0;
                pk.y = *(unsigned int*)&p1;
                *(uint2*)&Bs[r][c0 + q * 4] = pk;
            }
        }
        __syncthreads();

        #pragma unroll
        for (int kk = 0; kk < 4; kk++) {
            uint32_t a0, a1, a2, a3;
            {
                int j = lane >> 3;
                uint32_t addr = smem_u32(&As[warp * 16 + (lane & 7) + 8 * (j & 1)]
                                            [kk * 16 + 8 * (j >> 1)]);
                asm volatile("ldmatrix.sync.aligned.m8n8.x4.shared.b16 {%0,%1,%2,%3}, [%4];"
                             : "=r"(a0), "=r"(a1), "=r"(a2), "=r"(a3) : "r"(addr));
            }
            #pragma unroll
            for (int nt = 0; nt < 8; nt += 2) {
                uint32_t b0, b1, b2, b3;
                int j = lane >> 3;
                uint32_t addr = smem_u32(&Bs[kk * 16 + (lane & 7) + 8 * (j & 1)]
                                            [nt * 8 + 8 * (j >> 1)]);
                asm volatile("ldmatrix.sync.aligned.m8n8.x4.trans.shared.b16 {%0,%1,%2,%3}, [%4];"
                             : "=r"(b0), "=r"(b1), "=r"(b2), "=r"(b3) : "r"(addr));
                asm volatile("mma.sync.aligned.m16n8k16.row.col.f32.f16.f16.f32 "
                             "{%0,%1,%2,%3}, {%4,%5,%6,%7}, {%8,%9}, {%0,%1,%2,%3};"
                             : "+f"(d[nt][0]), "+f"(d[nt][1]), "+f"(d[nt][2]), "+f"(d[nt][3])
                             : "r"(a0), "r"(a1), "r"(a2), "r"(a3), "r"(b0), "r"(b1));
                asm volatile("mma.sync.aligned.m16n8k16.row.col.f32.f16.f16.f32 "
                             "{%0,%1,%2,%3}, {%4,%5,%6,%7}, {%8,%9}, {%0,%1,%2,%3};"
                             : "+f"(d[nt+1][0]), "+f"(d[nt+1][1]), "+f"(d[nt+1][2]), "+f"(d[nt+1][3])
                             : "r"(a0), "r"(a1), "r"(a2), "r"(a3), "r"(b2), "r"(b3));
            }
        }
    }

    int g = lane >> 2, q = lane & 3;
    int row0 = brow + warp * 16 + g;
    int row1 = row0 + 8;
    float d0 = (row0 < NN) ? g_dis[row0] : 0.f;
    float d1 = (row1 < NN) ? g_dis[row1] : 0.f;
    #pragma unroll
    for (int nt = 0; nt < 8; nt++) {
        int c = nt * 8 + 2 * q;
        if (row0 < NN)
            *(float2*)&g_hn[(size_t)row0 * HD + c] = make_float2(d[nt][0] * d0, d[nt][1] * d0);
        if (row1 < NN)
            *(float2*)&g_hn[(size_t)row1 * HD + c] = make_float2(d[nt][2] * d1, d[nt][3] * d1);
    }
}

// ---------------- gather: paired-lane float4 gathers + aligned int4 colidx, pipelined ----------------
// lanes 0-15 gather even edge, lanes 16-31 odd edge; each lane owns 4 feature cols.
// Returns the full aggregated float4 (incl. self term) valid on lanes 0-15.
__device__ __forceinline__ float4 warp_gather_sum4(int v, int lane) {
    int beg = g_rowptr[v], end = g_rowptr[v + 1];   // both multiples of 4
    int col4 = (lane & 15) * 4;
    bool lo = lane < 16;
    float4 acc = make_float4(0.f, 0.f, 0.f, 0.f);

    int niter = (end - beg) >> 2;
    if (niter) {
        int4 c = *(const int4*)&g_colidx[beg];
        int p = beg + 4;
        for (int it = 1; it < niter; it++, p += 4) {
            int4 n = *(const int4*)&g_colidx[p];      // prefetch next 4 edges
            int u0 = lo ? c.x : c.y;
            int u1 = lo ? c.z : c.w;
            float4 t0 = *(const float4*)&g_hn[(size_t)u0 * HD + col4];
            float4 t1 = *(const float4*)&g_hn[(size_t)u1 * HD + col4];
            acc.x += t0.x + t1.x; acc.y += t0.y + t1.y;
            acc.z += t0.z + t1.z; acc.w += t0.w + t1.w;
            c = n;
        }
        int u0 = lo ? c.x : c.y;
        int u1 = lo ? c.z : c.w;
        float4 t0 = *(const float4*)&g_hn[(size_t)u0 * HD + col4];
        float4 t1 = *(const float4*)&g_hn[(size_t)u1 * HD + col4];
        acc.x += t0.x + t1.x; acc.y += t0.y + t1.y;
        acc.z += t0.z + t1.z; acc.w += t0.w + t1.w;
    }

    // fold odd-edge half onto lanes 0-15
    acc.x += __shfl_xor_sync(0xffffffffu, acc.x, 16);
    acc.y += __shfl_xor_sync(0xffffffffu, acc.y, 16);
    acc.z += __shfl_xor_sync(0xffffffffu, acc.z, 16);
    acc.w += __shfl_xor_sync(0xffffffffu, acc.w, 16);

    if (lo) {   // self-loop term
        float4 s = *(const float4*)&g_hn[(size_t)v * HD + col4];
        acc.x += s.x; acc.y += s.y; acc.z += s.z; acc.w += s.w;
    }
    return acc;
}

__global__ void __launch_bounds__(256, 8)
k_agg(const float* __restrict__ bias, int first) {
    int warp = (blockIdx.x * blockDim.x + threadIdx.x) >> 5;
    int lane = threadIdx.x & 31;
    if (warp >= NN) return;
    int v = warp;

    float4 acc = warp_gather_sum4(v, lane);
    if (lane < 16) {
        int col4 = lane * 4;
        float d = g_dis[v];
        float4 b = *(const float4*)&bias[col4];
        float h0 = fmaxf(fmaf(d, acc.x, b.x), 0.f);
        float h1 = fmaxf(fmaf(d, acc.y, b.y), 0.f);
        float h2 = fmaxf(fmaf(d, acc.z, b.z), 0.f);
        float h3 = fmaxf(fmaf(d, acc.w, b.w), 0.f);

        size_t fo = (size_t)v * HD + col4;
        __half2 p0 = __floats2half2_rn(h0, h1);
        __half2 p1 = __floats2half2_rn(h2, h3);
        uint2 pk;
        pk.x = *(unsigned int*)&p0;
        pk.y = *(unsigned int*)&p1;
        *(uint2*)&g_h16[fo] = pk;

        if (first) {
            *(float4*)&g_jk[fo] = make_float4(h0, h1, h2, h3);
        } else {
            float4 j = *(const float4*)&g_jk[fo];
            *(float4*)&g_jk[fo] = make_float4(fmaxf(j.x, h0), fmaxf(j.y, h1),
                                              fmaxf(j.z, h2), fmaxf(j.w, h3));
        }
    }
}

// ---------------- last layer fused with head ----------------
__global__ void __launch_bounds__(256, 8)
k_agg_proj(const float* __restrict__ bias,
           const float* __restrict__ fcw, const float* __restrict__ fcb,
           float* __restrict__ out) {
    __shared__ float Wsm[HD * CC];
    __shared__ float bsm[CC];
    int tid = threadIdx.x;
    for (int i = tid; i < HD * CC; i += blockDim.x) Wsm[i] = fcw[i];
    if (tid < CC) bsm[tid] = fcb[tid];
    __syncthreads();

    int warp = (blockIdx.x * blockDim.x + tid) >> 5;
    int lane = tid & 31;
    if (warp >= NN) return;
    int v = warp;

    float4 acc = warp_gather_sum4(v, lane);
    float4 jv = make_float4(0.f, 0.f, 0.f, 0.f);
    if (lane < 16) {
        int col4 = lane * 4;
        float d = g_dis[v];
        float4 b = *(const float4*)&bias[col4];
        float h0 = fmaxf(fmaf(d, acc.x, b.x), 0.f);
        float h1 = fmaxf(fmaf(d, acc.y, b.y), 0.f);
        float h2 = fmaxf(fmaf(d, acc.z, b.z), 0.f);
        float h3 = fmaxf(fmaf(d, acc.w, b.w), 0.f);
        float4 j = *(const float4*)&g_jk[(size_t)v * HD + col4];
        jv = make_float4(fmaxf(j.x, h0), fmaxf(j.y, h1), fmaxf(j.z, h2), fmaxf(j.w, h3));
    }

    // projection: jk cols live 4/lane on lanes 0-15
    bool act = lane < 20;
    int c0 = lane * 2;
    float a0 = 0.f, a1 = 0.f;
    #pragma unroll
    for (int k = 0; k < HD; k++) {
        float comp = ((k & 3) == 0) ? jv.x : ((k & 3) == 1) ? jv.y
                   : ((k & 3) == 2) ? jv.z : jv.w;             // compile-time select (unrolled)
        float hv = __shfl_sync(0xffffffffu, comp, k >> 2);
        if (act) {
            float2 w = *(const float2*)&Wsm[k * CC + c0];
            a0 = fmaf(hv, w.x, a0);
            a1 = fmaf(hv, w.y, a1);
        }
    }
    if (act) { a0 += bsm[c0]; a1 += bsm[c0 + 1]; }

    float m = act ? fmaxf(a0, a1) : -INFINITY;
    #pragma unroll
    for (int off = 16; off; off >>= 1) m = fmaxf(m, __shfl_xor_sync(0xffffffffu, m, off));
    float s = act ? (expf(a0 - m) + expf(a1 - m)) : 0.f;
    #pragma unroll
    for (int off = 16; off; off >>= 1) s += __shfl_xor_sync(0xffffffffu, s, off);
    float lse = m + logf(s);

    if (act) {
        float2 o = make_float2(a0 - lse, a1 - lse);
        *(float2*)&out[(size_t)v * CC + c0] = o;
    }
}

// ---------------- launch ----------------
extern "C" void kernel_launch(void* const* d_in, const int* in_sizes, int n_in,
                              void* d_out, int out_size) {
    const float* x   = (const float*)d_in[0];
    const int*   ei  = (const int*)  d_in[1];
    const float* W0  = (const float*)d_in[2];
    const float* Ws  = (const float*)d_in[3];
    const float* bs  = (const float*)d_in[4];
    const float* fcw = (const float*)d_in[5];
    const float* fcb = (const float*)d_in[6];
    float* out = (float*)d_out;

    const int* src = ei;         // edge_index[0]
    const int* dst = ei + EE;    // edge_index[1]

    int* degp;
    cudaGetSymbolAddress((void**)&degp, g_deg);

    // CSR build (padded to multiples of 4 per node)
    cudaMemsetAsync(degp, 0, NN * sizeof(int));
    k_count  <<<(EE / 4 + 255) / 256, 256>>>(dst);
    k_scan1  <<<NB, 256>>>();
    k_scan2  <<<1, 512>>>();
    k_scan3  <<<NB, 256>>>();
    k_scatter<<<(EE / 4 + 255) / 256, 256>>>(src, dst);
    k_pad    <<<NB, 256>>>();

    const int GEMM_GRID = (NN + 127) / 128;  // 782 (128-row tiles)
    const int AGG_GRID  = (NN + 7) / 8;      // 8 warps per 256-thread block

    // layer 0: x (N x 128) @ W0
    k_gemm_mma<FIN, true><<<GEMM_GRID, 256>>>(x, W0);
    k_agg<<<AGG_GRID, 256>>>(bs + 0 * HD, 1);

    // layers 1..4
    for (int l = 1; l < LL - 1; l++) {
        k_gemm_mma<HD, false><<<GEMM_GRID, 256>>>(nullptr, Ws + (size_t)(l - 1) * HD * HD);
        k_agg<<<AGG_GRID, 256>>>(bs + (size_t)l * HD, 0);
    }
    // layer 5: aggregation fused with projection head
    k_gemm_mma<HD, false><<<GEMM_GRID, 256>>>(nullptr, Ws + (size_t)(LL - 2) * HD * HD);
    k_agg_proj<<<AGG_GRID, 256>>>(bs + (size_t)(LL - 1) * HD, fcw, fcb, out);
}